// round 10
// baseline (speedup 1.0000x reference)
#include <cuda_runtime.h>
#include <cuda_bf16.h>
#include <cstdint>
#include <cstddef>

#define NDIM 4096
#define DDIM 256
#define NMTOT ((size_t)NDIM * (size_t)NDIM)
#define EPS_R 0.05f
#define N_SINK 30
#define N_FGW 5

// ---------------- device scratch ----------------
__device__ float g_Dgen [NDIM * NDIM];
__device__ float g_Dreal[NDIM * NDIM];
__device__ float g_CW   [NDIM * NDIM];
__device__ float g_CGW  [NDIM * NDIM];
__device__ float g_Kmat [NDIM * NDIM];
__device__ __nv_bfloat16 g_Dg_h[NDIM * NDIM], g_Dg_m[NDIM * NDIM], g_Dg_l[NDIM * NDIM];
__device__ __nv_bfloat16 g_Dr_h[NDIM * NDIM], g_Dr_m[NDIM * NDIM], g_Dr_l[NDIM * NDIM];
__device__ __nv_bfloat16 g_Pt_h[NDIM * NDIM], g_Pt_m[NDIM * NDIM], g_Pt_l[NDIM * NDIM];
__device__ __nv_bfloat16 g_T_h [NDIM * NDIM], g_T_m [NDIM * NDIM], g_T_l [NDIM * NDIM];
__device__ float g_x2g[NDIM], g_x2r[NDIM];
__device__ float g_sg2[NDIM], g_sr2[NDIM];
__device__ float g_rg [NDIM], g_rr [NDIM];
__device__ float g_mu [NDIM], g_nu [NDIM];
__device__ float g_u  [NDIM], g_v  [NDIM];
__device__ float g_colpart[32 * NDIM];
__device__ float g_part[8192];
__device__ float g_scal[8];   // 0:cwmax 1:gmax 2:cmax 3:S

// ---------------- helpers ----------------
__device__ __forceinline__ uint32_t pack2(float f0, float f1) {
    __nv_bfloat162 p; p.x = __float2bfloat16(f0); p.y = __float2bfloat16(f1);
    return *reinterpret_cast<uint32_t*>(&p);
}
__device__ __forceinline__ void ldm_x4(uint32_t* r, uint32_t a) {
    asm volatile("ldmatrix.sync.aligned.m8n8.x4.shared.b16 {%0,%1,%2,%3}, [%4];"
        : "=r"(r[0]), "=r"(r[1]), "=r"(r[2]), "=r"(r[3]) : "r"(a));
}
__device__ __forceinline__ void mma16816(float* c, const uint32_t* a, const uint32_t* b) {
    asm volatile("mma.sync.aligned.m16n8k16.row.col.f32.bf16.bf16.f32 "
        "{%0,%1,%2,%3}, {%4,%5,%6,%7}, {%8,%9}, {%0,%1,%2,%3};"
        : "+f"(c[0]), "+f"(c[1]), "+f"(c[2]), "+f"(c[3])
        : "r"(a[0]), "r"(a[1]), "r"(a[2]), "r"(a[3]), "r"(b[0]), "r"(b[1]));
}
__device__ __forceinline__ uint32_t smem_u32(const void* p) {
    uint32_t a;
    asm("{ .reg .u64 t; cvta.to.shared.u64 t, %1; cvt.u32.u64 %0, t; }" : "=r"(a) : "l"(p));
    return a;
}
// exact fp32 -> bf16 (hi, mid, lo): x == hi + mid + lo exactly
__device__ __forceinline__ void split3(float x, __nv_bfloat16& h, __nv_bfloat16& m, __nv_bfloat16& l) {
    h = __float2bfloat16(x);
    float r1 = x - __bfloat162float(h);
    m = __float2bfloat16(r1);
    l = __float2bfloat16(r1 - __bfloat162float(m));
}
#define CP16(dst, src) asm volatile("cp.async.cg.shared.global [%0], [%1], 16;" :: "r"(dst), "l"(src) : "memory")
#define CPC() asm volatile("cp.async.commit_group;" ::: "memory")
#define CPW(n) asm volatile("cp.async.wait_group %0;" :: "n"(n) : "memory")

// ---------------- reductions ----------------
template<int BS>
__device__ __forceinline__ float bsum(float v) {
    static __shared__ float sh[BS];
    int t = threadIdx.x;
    sh[t] = v; __syncthreads();
#pragma unroll
    for (int s = BS / 2; s >= 64; s >>= 1) { if (t < s) sh[t] += sh[t + s]; __syncthreads(); }
    float x = 0.f;
    if (t < 32) {
        x = sh[t] + sh[t + 32];
#pragma unroll
        for (int o = 16; o; o >>= 1) x += __shfl_down_sync(0xffffffffu, x, o);
    }
    return x;
}
template<int BS>
__device__ __forceinline__ float bmax(float v) {
    static __shared__ float sh[BS];
    int t = threadIdx.x;
    sh[t] = v; __syncthreads();
#pragma unroll
    for (int s = BS / 2; s >= 64; s >>= 1) { if (t < s) sh[t] = fmaxf(sh[t], sh[t + s]); __syncthreads(); }
    float x = -3.402823466e38f;
    if (t < 32) {
        x = fmaxf(sh[t], sh[t + 32]);
#pragma unroll
        for (int o = 16; o; o >>= 1) x = fmaxf(x, __shfl_down_sync(0xffffffffu, x, o));
    }
    return x;
}

// ---------------- exact-split bf16 GEMM, two-level accumulation -----------
// C[m,n] = sum_k A[m,k]*B[n,k], operands split exactly into h+m+l bf16.
// Terms kept: hh+hm+mh+mm+hl+lh. Working acc is flushed into accS every
// 16 k-chunks (pairwise accumulation) to kill fp32 rounding noise.
// MODE 0: emit C exactly re-split into Oh/Om/Ol. MODE 1: CGW epilogue + gmax.
#define STG_T 10240               // one tile: 128 rows * 80B (64B data + 16B pad)
#define STG_S (6 * STG_T)
#define SMEM_MM (3 * STG_S)       // 184320
#define BKT 32
#define NTILES (NDIM / BKT)       // 128

template<int MODE>
__global__ void __launch_bounds__(256, 1)
mma_gemm_kernel(const __nv_bfloat16* __restrict__ Ah_, const __nv_bfloat16* __restrict__ Am_,
                const __nv_bfloat16* __restrict__ Al_,
                const __nv_bfloat16* __restrict__ Bh_, const __nv_bfloat16* __restrict__ Bm_,
                const __nv_bfloat16* __restrict__ Bl_,
                __nv_bfloat16* __restrict__ Oh, __nv_bfloat16* __restrict__ Om,
                __nv_bfloat16* __restrict__ Ol,
                float* __restrict__ Cout, float* __restrict__ partials)
{
    extern __shared__ char smem[];
    const uint32_t sb = smem_u32(smem);
    const int tid = threadIdx.x, warp = tid >> 5, lane = tid & 31;
    const int bm = blockIdx.y << 7, bn = blockIdx.x << 7;
    const int wm = (warp >> 2) << 6, wn = (warp & 3) << 5;  // warp tile 64x32

    const char* srcs[6] = {
        (const char*)(Ah_ + (size_t)bm * NDIM), (const char*)(Am_ + (size_t)bm * NDIM),
        (const char*)(Al_ + (size_t)bm * NDIM),
        (const char*)(Bh_ + (size_t)bn * NDIM), (const char*)(Bm_ + (size_t)bn * NDIM),
        (const char*)(Bl_ + (size_t)bn * NDIM) };

    auto load_stage = [&](int slot, int kt) {
        const uint32_t sbase = sb + slot * STG_S;
        const size_t ko = (size_t)kt * (BKT * 2);
#pragma unroll
        for (int i = 0; i < 12; i++) {
            const int tile = i >> 1;
            const int wc = ((i & 1) << 8) + tid;
            const int row = wc >> 2, cc = wc & 3;
            uint32_t dst = sbase + tile * STG_T + row * 80 + (cc << 4);
            const char* src = srcs[tile] + (size_t)row * (NDIM * 2) + ko + (cc << 4);
            CP16(dst, src);
        }
    };

    float acc[4][4][4], accS[4][4][4];
#pragma unroll
    for (int a = 0; a < 4; a++)
#pragma unroll
        for (int b = 0; b < 4; b++)
#pragma unroll
            for (int c = 0; c < 4; c++) { acc[a][b][c] = 0.f; accS[a][b][c] = 0.f; }

    load_stage(0, 0); CPC();
    load_stage(1, 1); CPC();

    const int grp = lane >> 3, l8 = lane & 7;

    for (int kt = 0; kt < NTILES; kt++) {
        CPW(1);
        __syncthreads();
        if (kt + 2 < NTILES) load_stage((kt + 2) % 3, kt + 2);
        CPC();
        const uint32_t stb = sb + (kt % 3) * STG_S;
#pragma unroll
        for (int ks = 0; ks < 2; ks++) {
            uint32_t ah[4][4], am[4][4], al[4][4];
            uint32_t bh[4][2], bmm[4][2], bl[4][2], t[4];
            const uint32_t acol = (ks << 5) + ((grp >> 1) << 4);
#pragma unroll
            for (int mi = 0; mi < 4; mi++) {
                uint32_t ro = (uint32_t)(wm + (mi << 4) + ((grp & 1) << 3) + l8) * 80 + acol;
                ldm_x4(ah[mi], stb + 0 * STG_T + ro);
                ldm_x4(am[mi], stb + 1 * STG_T + ro);
                ldm_x4(al[mi], stb + 2 * STG_T + ro);
            }
            const uint32_t bcol = (ks << 5) + ((grp & 1) << 4);
#pragma unroll
            for (int np = 0; np < 2; np++) {
                uint32_t ro = (uint32_t)(wn + (np << 4) + ((grp >> 1) << 3) + l8) * 80 + bcol;
                ldm_x4(t, stb + 3 * STG_T + ro);
                bh[2 * np][0] = t[0]; bh[2 * np][1] = t[1];
                bh[2 * np + 1][0] = t[2]; bh[2 * np + 1][1] = t[3];
                ldm_x4(t, stb + 4 * STG_T + ro);
                bmm[2 * np][0] = t[0]; bmm[2 * np][1] = t[1];
                bmm[2 * np + 1][0] = t[2]; bmm[2 * np + 1][1] = t[3];
                ldm_x4(t, stb + 5 * STG_T + ro);
                bl[2 * np][0] = t[0]; bl[2 * np][1] = t[1];
                bl[2 * np + 1][0] = t[2]; bl[2 * np + 1][1] = t[3];
            }
#pragma unroll
            for (int mi = 0; mi < 4; mi++)
#pragma unroll
                for (int ni = 0; ni < 4; ni++) {
                    mma16816(acc[mi][ni], ah[mi], bh[ni]);
                    mma16816(acc[mi][ni], ah[mi], bmm[ni]);
                    mma16816(acc[mi][ni], am[mi], bh[ni]);
                    mma16816(acc[mi][ni], am[mi], bmm[ni]);
                    mma16816(acc[mi][ni], ah[mi], bl[ni]);
                    mma16816(acc[mi][ni], al[mi], bh[ni]);
                }
        }
        if ((kt & 15) == 15) {   // pairwise flush: kills accumulation noise
#pragma unroll
            for (int a = 0; a < 4; a++)
#pragma unroll
                for (int b = 0; b < 4; b++)
#pragma unroll
                    for (int c = 0; c < 4; c++) { accS[a][b][c] += acc[a][b][c]; acc[a][b][c] = 0.f; }
        }
    }

    float lmax = 0.f;
#pragma unroll
    for (int mi = 0; mi < 4; mi++) {
        const int r1 = bm + wm + (mi << 4) + (lane >> 2);
        const int r2 = r1 + 8;
        float sgA = 0.f, muA = 0.f, sgB = 0.f, muB = 0.f;
        if (MODE == 1) { sgA = g_sg2[r1]; muA = g_mu[r1]; sgB = g_sg2[r2]; muB = g_mu[r2]; }
#pragma unroll
        for (int ni = 0; ni < 4; ni++) {
            const int n1 = bn + wn + (ni << 3) + ((lane & 3) << 1);
            const float c0 = accS[mi][ni][0], c1 = accS[mi][ni][1];
            const float c2 = accS[mi][ni][2], c3 = accS[mi][ni][3];
            if (MODE == 0) {
                __nv_bfloat16 h0, m0, l0, h1, m1, l1;
                split3(c0, h0, m0, l0); split3(c1, h1, m1, l1);
                __nv_bfloat162 hm01{m0, m1}, hl01{l0, l1};
                *(uint32_t*)(Oh + (size_t)r1 * NDIM + n1) = pack2(c0, c1);
                *(uint32_t*)(Om + (size_t)r1 * NDIM + n1) = *(uint32_t*)&hm01;
                *(uint32_t*)(Ol + (size_t)r1 * NDIM + n1) = *(uint32_t*)&hl01;
                __nv_bfloat16 h2, m2, l2, h3, m3, l3;
                split3(c2, h2, m2, l2); split3(c3, h3, m3, l3);
                __nv_bfloat162 hm23{m2, m3}, hl23{l2, l3};
                *(uint32_t*)(Oh + (size_t)r2 * NDIM + n1) = pack2(c2, c3);
                *(uint32_t*)(Om + (size_t)r2 * NDIM + n1) = *(uint32_t*)&hm23;
                *(uint32_t*)(Ol + (size_t)r2 * NDIM + n1) = *(uint32_t*)&hl23;
            } else {
                const float nu1 = g_nu[n1], nu2 = g_nu[n1 + 1];
                const float s1 = g_sr2[n1], s2 = g_sr2[n1 + 1];
                float v0 = sgA * nu1 + muA * s1 - 2.f * c0;
                float v1 = sgA * nu2 + muA * s2 - 2.f * c1;
                float v2 = sgB * nu1 + muB * s1 - 2.f * c2;
                float v3 = sgB * nu2 + muB * s2 - 2.f * c3;
                lmax = fmaxf(fmaxf(lmax, fabsf(v0)), fmaxf(fabsf(v1), fmaxf(fabsf(v2), fabsf(v3))));
                *(float2*)(Cout + (size_t)r1 * NDIM + n1) = make_float2(v0, v1);
                *(float2*)(Cout + (size_t)r2 * NDIM + n1) = make_float2(v2, v3);
            }
        }
    }
    if (MODE == 1) {
        float mm = bmax<256>(lmax);
        if (tid == 0) partials[blockIdx.y * gridDim.x + blockIdx.x] = mm;
    }
}

// ---------------- small kernels ----------------
__global__ void sqnorm_kernel(const float* __restrict__ X, float* __restrict__ out) {
    int i = blockIdx.x;
    float4 a = ((const float4*)(X + (size_t)i * DDIM))[threadIdx.x];
    float s = a.x * a.x + a.y * a.y + a.z * a.z + a.w * a.w;
    s = bsum<64>(s);
    if (threadIdx.x == 0) out[i] = s;
}

__global__ void fill_kernel(float* __restrict__ p, float val, size_t n) {
    size_t stride = (size_t)gridDim.x * blockDim.x;
    for (size_t i = (size_t)blockIdx.x * blockDim.x + threadIdx.x; i < n; i += stride) p[i] = val;
}

__global__ void row_sum_kernel(const float* __restrict__ M, float* __restrict__ out) {
    int i = blockIdx.x;
    const float4* rp = (const float4*)(M + (size_t)i * NDIM);
    float s = 0.f;
    for (int j = threadIdx.x; j < NDIM / 4; j += 256) { float4 a = rp[j]; s += a.x + a.y + a.z + a.w; }
    s = bsum<256>(s);
    if (threadIdx.x == 0) out[i] = s;
}

__global__ void row_sumsq_kernel(const float* __restrict__ M, float* __restrict__ out) {
    int i = blockIdx.x;
    const float4* rp = (const float4*)(M + (size_t)i * NDIM);
    float s = 0.f;
    for (int j = threadIdx.x; j < NDIM / 4; j += 256) {
        float4 a = rp[j];
        s += a.x * a.x + a.y * a.y + a.z * a.z + a.w * a.w;
    }
    s = bsum<256>(s);
    if (threadIdx.x == 0) out[i] = s;
}

__global__ void split3_kernel(const float* __restrict__ src, __nv_bfloat16* __restrict__ dh,
                              __nv_bfloat16* __restrict__ dm, __nv_bfloat16* __restrict__ dl) {
    size_t stride = (size_t)gridDim.x * blockDim.x;
    const float2* sp = (const float2*)src;
    uint32_t* hp = (uint32_t*)dh; uint32_t* mp = (uint32_t*)dm; uint32_t* lp = (uint32_t*)dl;
    for (size_t i = (size_t)blockIdx.x * blockDim.x + threadIdx.x; i < NMTOT / 2; i += stride) {
        float2 f = sp[i];
        __nv_bfloat16 h0, m0, l0, h1, m1, l1;
        split3(f.x, h0, m0, l0); split3(f.y, h1, m1, l1);
        __nv_bfloat162 hh{h0, h1}, mm{m0, m1}, ll{l0, l1};
        hp[i] = *(uint32_t*)&hh; mp[i] = *(uint32_t*)&mm; lp[i] = *(uint32_t*)&ll;
    }
}

__global__ void transpose_split3_kernel(const float* __restrict__ src,
                                        __nv_bfloat16* __restrict__ dh,
                                        __nv_bfloat16* __restrict__ dm,
                                        __nv_bfloat16* __restrict__ dl) {
    __shared__ float tile[32][33];
    const int x0 = blockIdx.x << 5, y0 = blockIdx.y << 5;
    const int tx = threadIdx.x, ty = threadIdx.y;
#pragma unroll
    for (int r = ty; r < 32; r += 8)
        tile[r][tx] = src[(size_t)(y0 + r) * NDIM + x0 + tx];
    __syncthreads();
#pragma unroll
    for (int rn = ty; rn < 32; rn += 8) {
        float f = tile[tx][rn];
        __nv_bfloat16 h, m, l;
        split3(f, h, m, l);
        size_t o = (size_t)(x0 + rn) * NDIM + y0 + tx;
        dh[o] = h; dm[o] = m; dl[o] = l;
    }
}

__global__ void colpart_sum_kernel(const float* __restrict__ M) {
    int col = (blockIdx.x << 8) + threadIdx.x;
    int r0 = blockIdx.y << 7;
    const float* base = M + (size_t)r0 * NDIM + col;
    float s0 = 0.f, s1 = 0.f, s2 = 0.f, s3 = 0.f;
#pragma unroll 8
    for (int i = 0; i < 128; i += 4) {
        s0 += base[(size_t)(i + 0) * NDIM]; s1 += base[(size_t)(i + 1) * NDIM];
        s2 += base[(size_t)(i + 2) * NDIM]; s3 += base[(size_t)(i + 3) * NDIM];
    }
    g_colpart[(blockIdx.y << 12) + col] = (s0 + s1) + (s2 + s3);
}

__global__ void sink_colpart_kernel() {
    int col = (blockIdx.x << 8) + threadIdx.x;
    int r0 = blockIdx.y << 7;
    const float* base = g_Kmat + (size_t)r0 * NDIM + col;
    float s0 = 0.f, s1 = 0.f, s2 = 0.f, s3 = 0.f;
#pragma unroll 8
    for (int i = 0; i < 128; i += 4) {
        s0 += base[(size_t)(i + 0) * NDIM] * g_u[r0 + i + 0];
        s1 += base[(size_t)(i + 1) * NDIM] * g_u[r0 + i + 1];
        s2 += base[(size_t)(i + 2) * NDIM] * g_u[r0 + i + 2];
        s3 += base[(size_t)(i + 3) * NDIM] * g_u[r0 + i + 3];
    }
    g_colpart[(blockIdx.y << 12) + col] = (s0 + s1) + (s2 + s3);
}

__global__ void colfin_kernel(float* __restrict__ out, int isV) {
    int col = (blockIdx.x << 8) + threadIdx.x;
    float s = 0.f;
#pragma unroll
    for (int p = 0; p < 32; p++) s += g_colpart[(p << 12) + col];
    out[col] = isV ? ((1.0f / NDIM) / s) : s;
}

__global__ void sink_row_kernel() {
    int i = blockIdx.x;
    const float4* kr = (const float4*)(g_Kmat + (size_t)i * NDIM);
    const float4* vv = (const float4*)g_v;
    float s = 0.f;
    for (int j = threadIdx.x; j < NDIM / 4; j += 256) {
        float4 k = kr[j], w = vv[j];
        s += k.x * w.x + k.y * w.y + k.z * w.z + k.w * w.w;
    }
    s = bsum<256>(s);
    if (threadIdx.x == 0) g_u[i] = (1.0f / NDIM) / s;
}

__global__ void gmax0_kernel(float* __restrict__ partials) {
    const int i = blockIdx.x;
    const float invn = 1.0f / NDIM;
    const float ai = g_sg2[i] * invn;
    const float gi = 2.0f * g_rg[i] * invn * invn;
    const float4* sp = (const float4*)g_sr2;
    const float4* rp = (const float4*)g_rr;
    float m = 0.f;
    for (int j = threadIdx.x; j < NDIM / 4; j += 256) {
        float4 s = sp[j], rr = rp[j];
        m = fmaxf(m, fabsf(ai + s.x * invn - gi * rr.x));
        m = fmaxf(m, fabsf(ai + s.y * invn - gi * rr.y));
        m = fmaxf(m, fabsf(ai + s.z * invn - gi * rr.z));
        m = fmaxf(m, fabsf(ai + s.w * invn - gi * rr.w));
    }
    m = bmax<256>(m);
    if (threadIdx.x == 0) partials[i] = m;
}

template<int ITER0>
__global__ void fusedmax_kernel(float* __restrict__ partials) {
    const int i = blockIdx.x;
    const float invcw = (g_scal[0] > 0.f) ? 1.f / g_scal[0] : 1.f;
    const float invg  = (g_scal[1] > 0.f) ? 1.f / g_scal[1] : 1.f;
    const float invn = 1.0f / NDIM;
    const float ai = g_sg2[i] * invn;
    const float gi = 2.0f * g_rg[i] * invn * invn;
    const float4* cwp = (const float4*)(g_CW + (size_t)i * NDIM);
    const float4* cgp = (const float4*)(g_CGW + (size_t)i * NDIM);
    const float4* sp = (const float4*)g_sr2;
    const float4* rp = (const float4*)g_rr;
    float m = -3.402823466e38f;
    for (int j = threadIdx.x; j < NDIM / 4; j += 256) {
        float4 cw = cwp[j], cg;
        if (ITER0) {
            float4 s = sp[j], rr = rp[j];
            cg.x = ai + s.x * invn - gi * rr.x; cg.y = ai + s.y * invn - gi * rr.y;
            cg.z = ai + s.z * invn - gi * rr.z; cg.w = ai + s.w * invn - gi * rr.w;
        } else cg = cgp[j];
        m = fmaxf(m, 0.5f * cw.x * invcw + 0.5f * cg.x * invg);
        m = fmaxf(m, 0.5f * cw.y * invcw + 0.5f * cg.y * invg);
        m = fmaxf(m, 0.5f * cw.z * invcw + 0.5f * cg.z * invg);
        m = fmaxf(m, 0.5f * cw.w * invcw + 0.5f * cg.w * invg);
    }
    m = bmax<256>(m);
    if (threadIdx.x == 0) partials[i] = m;
}

template<int ITER0>
__global__ void kexp_kernel() {
    const int i = blockIdx.x;
    const float invcw = (g_scal[0] > 0.f) ? 1.f / g_scal[0] : 1.f;
    const float invg  = (g_scal[1] > 0.f) ? 1.f / g_scal[1] : 1.f;
    const float cm = g_scal[2];
    const float sc = (cm > 0.f) ? (-1.f / ((cm + 1e-8f) * EPS_R)) : (-1.f / EPS_R);
    const float invn = 1.0f / NDIM;
    const float ai = g_sg2[i] * invn;
    const float gi = 2.0f * g_rg[i] * invn * invn;
    const float4* cwp = (const float4*)(g_CW + (size_t)i * NDIM);
    const float4* cgp = (const float4*)(g_CGW + (size_t)i * NDIM);
    const float4* sp = (const float4*)g_sr2;
    const float4* rp = (const float4*)g_rr;
    float4* kp = (float4*)(g_Kmat + (size_t)i * NDIM);
    for (int j = threadIdx.x; j < NDIM / 4; j += 256) {
        float4 cw = cwp[j], cg;
        if (ITER0) {
            float4 s = sp[j], rr = rp[j];
            cg.x = ai + s.x * invn - gi * rr.x; cg.y = ai + s.y * invn - gi * rr.y;
            cg.z = ai + s.z * invn - gi * rr.z; cg.w = ai + s.w * invn - gi * rr.w;
        } else cg = cgp[j];
        float4 o;
        o.x = __expf((0.5f * cw.x * invcw + 0.5f * cg.x * invg) * sc);
        o.y = __expf((0.5f * cw.y * invcw + 0.5f * cg.y * invg) * sc);
        o.z = __expf((0.5f * cw.z * invcw + 0.5f * cg.z * invg) * sc);
        o.w = __expf((0.5f * cw.w * invcw + 0.5f * cg.w * invg) * sc);
        kp[j] = o;
    }
}

__global__ void pwrite_kernel(float* __restrict__ P, float* __restrict__ partials) {
    int i = blockIdx.x;
    float ui = g_u[i];
    const float4* kr = (const float4*)(g_Kmat + (size_t)i * NDIM);
    const float4* vv = (const float4*)g_v;
    float4* pr = (float4*)(P + (size_t)i * NDIM);
    float s = 0.f;
    for (int j = threadIdx.x; j < NDIM / 4; j += 256) {
        float4 k = kr[j], w = vv[j];
        float4 o;
        o.x = ui * k.x * w.x; o.y = ui * k.y * w.y; o.z = ui * k.z * w.z; o.w = ui * k.w * w.w;
        pr[j] = o;
        s += o.x + o.y + o.z + o.w;
    }
    s = bsum<256>(s);
    if (threadIdx.x == 0) partials[i] = s;
}

__global__ void pscale_kernel(float* __restrict__ P) {
    float sc = 1.0f / (g_scal[3] + 1e-10f);
    size_t stride = (size_t)gridDim.x * blockDim.x;
    float4* pp = (float4*)P;
    for (size_t i = (size_t)blockIdx.x * blockDim.x + threadIdx.x; i < NMTOT / 4; i += stride) {
        float4 a = pp[i];
        a.x *= sc; a.y *= sc; a.z *= sc; a.w *= sc;
        pp[i] = a;
    }
}

__global__ void cfinal_kernel(float* __restrict__ out) {
    size_t stride = (size_t)gridDim.x * blockDim.x;
    const float4* cwp = (const float4*)g_CW;
    const float4* cgp = (const float4*)g_CGW;
    float4* op = (float4*)out;
    for (size_t i = (size_t)blockIdx.x * blockDim.x + threadIdx.x; i < NMTOT / 4; i += stride) {
        float4 cw = cwp[i], cg = cgp[i];
        op[i] = make_float4(0.5f * cw.x + 0.5f * cg.x, 0.5f * cw.y + 0.5f * cg.y,
                            0.5f * cw.z + 0.5f * cg.z, 0.5f * cw.w + 0.5f * cg.w);
    }
}

__global__ void reduce_max_kernel(const float* __restrict__ part, int n, int slot) {
    float m = -3.402823466e38f;
    for (int i = threadIdx.x; i < n; i += 1024) m = fmaxf(m, part[i]);
    m = bmax<1024>(m);
    if (threadIdx.x == 0) g_scal[slot] = m;
}

__global__ void reduce_sum_kernel(const float* __restrict__ part, int n, int slot) {
    float s = 0.f;
    for (int i = threadIdx.x; i < n; i += 1024) s += part[i];
    s = bsum<1024>(s);
    if (threadIdx.x == 0) g_scal[slot] = s;
}

// ---------------- SIMT SGEMM over D=256 (cdist / CW only) -----------------
template<int MODE>  // 2: sqrt(relu) ; 3: relu + max
__global__ void __launch_bounds__(256, 2)
sgemm_kernel(const float* __restrict__ A, const float* __restrict__ B,
             float* __restrict__ C, const float* __restrict__ vx,
             const float* __restrict__ vy, float* __restrict__ partials)
{
    __shared__ float As[16][132];
    __shared__ float Bs[16][132];
    const int tid = threadIdx.x;
    const int bm = blockIdx.y << 7, bn = blockIdx.x << 7;
    const int ty = tid >> 4, tx = tid & 15;
    const int lr = tid >> 2, lc = tid & 3;

    float acc[8][8];
#pragma unroll
    for (int i = 0; i < 8; i++)
#pragma unroll
        for (int j = 0; j < 8; j++) acc[i][j] = 0.f;

    for (int k0 = 0; k0 < DDIM; k0 += 16) {
#pragma unroll
        for (int h = 0; h < 2; h++) {
            int row = lr + (h << 6);
            float4 a = *(const float4*)(A + (size_t)(bm + row) * DDIM + (k0 + (lc << 2)));
            As[(lc << 2) + 0][row] = a.x; As[(lc << 2) + 1][row] = a.y;
            As[(lc << 2) + 2][row] = a.z; As[(lc << 2) + 3][row] = a.w;
            float4 b = *(const float4*)(B + (size_t)(bn + row) * DDIM + (k0 + (lc << 2)));
            Bs[(lc << 2) + 0][row] = b.x; Bs[(lc << 2) + 1][row] = b.y;
            Bs[(lc << 2) + 2][row] = b.z; Bs[(lc << 2) + 3][row] = b.w;
        }
        __syncthreads();
#pragma unroll
        for (int kk = 0; kk < 16; kk++) {
            float av[8], bv[8];
            *(float4*)&av[0] = *(const float4*)&As[kk][ty << 3];
            *(float4*)&av[4] = *(const float4*)&As[kk][(ty << 3) + 4];
            *(float4*)&bv[0] = *(const float4*)&Bs[kk][tx << 3];
            *(float4*)&bv[4] = *(const float4*)&Bs[kk][(tx << 3) + 4];
#pragma unroll
            for (int i = 0; i < 8; i++)
#pragma unroll
                for (int j = 0; j < 8; j++)
                    acc[i][j] = fmaf(av[i], bv[j], acc[i][j]);
        }
        __syncthreads();
    }

    float lmax = 0.f;
#pragma unroll
    for (int i = 0; i < 8; i++) {
        int gi = bm + (ty << 3) + i;
        float p0 = vx[gi];
        float ov[8];
#pragma unroll
        for (int j = 0; j < 8; j++) {
            int gj = bn + (tx << 3) + j;
            float d2 = fmaxf(p0 + vy[gj] - 2.f * acc[i][j], 0.f);
            if (MODE == 2) ov[j] = (d2 > 0.f) ? sqrtf(d2) : 0.f;
            else { ov[j] = d2; lmax = fmaxf(lmax, d2); }
        }
        float4* cp = (float4*)(C + (size_t)gi * NDIM + bn + (tx << 3));
        cp[0] = *(float4*)&ov[0];
        cp[1] = *(float4*)&ov[4];
    }
    if (MODE == 3) {
        float m = bmax<256>(lmax);
        if (tid == 0) partials[blockIdx.y * gridDim.x + blockIdx.x] = m;
    }
}

// ---------------- launch --------------------------------------------------
extern "C" void kernel_launch(void* const* d_in, const int* in_sizes, int n_in,
                              void* d_out, int out_size) {
    const float* fg = (const float*)d_in[0];
    const float* fr = (const float*)d_in[1];
    float* P  = (float*)d_out;
    float* Cf = (float*)d_out + NMTOT;

    float *Dgen, *Dreal, *CW, *CGW, *x2g, *x2r, *sg2, *sr2, *rg, *rr, *mu, *nu, *v, *part;
    __nv_bfloat16 *Dgh, *Dgm, *Dgl, *Drh, *Drm, *Drl, *Pth, *Ptm, *Ptl, *Th, *Tm, *Tl;
    cudaGetSymbolAddress((void**)&Dgen, g_Dgen);   cudaGetSymbolAddress((void**)&Dreal, g_Dreal);
    cudaGetSymbolAddress((void**)&CW, g_CW);       cudaGetSymbolAddress((void**)&CGW, g_CGW);
    cudaGetSymbolAddress((void**)&x2g, g_x2g);     cudaGetSymbolAddress((void**)&x2r, g_x2r);
    cudaGetSymbolAddress((void**)&sg2, g_sg2);     cudaGetSymbolAddress((void**)&sr2, g_sr2);
    cudaGetSymbolAddress((void**)&rg, g_rg);       cudaGetSymbolAddress((void**)&rr, g_rr);
    cudaGetSymbolAddress((void**)&mu, g_mu);       cudaGetSymbolAddress((void**)&nu, g_nu);
    cudaGetSymbolAddress((void**)&v, g_v);         cudaGetSymbolAddress((void**)&part, g_part);
    cudaGetSymbolAddress((void**)&Dgh, g_Dg_h);    cudaGetSymbolAddress((void**)&Dgm, g_Dg_m);
    cudaGetSymbolAddress((void**)&Dgl, g_Dg_l);    cudaGetSymbolAddress((void**)&Drh, g_Dr_h);
    cudaGetSymbolAddress((void**)&Drm, g_Dr_m);    cudaGetSymbolAddress((void**)&Drl, g_Dr_l);
    cudaGetSymbolAddress((void**)&Pth, g_Pt_h);    cudaGetSymbolAddress((void**)&Ptm, g_Pt_m);
    cudaGetSymbolAddress((void**)&Ptl, g_Pt_l);    cudaGetSymbolAddress((void**)&Th, g_T_h);
    cudaGetSymbolAddress((void**)&Tm, g_T_m);      cudaGetSymbolAddress((void**)&Tl, g_T_l);

    cudaFuncSetAttribute(mma_gemm_kernel<0>, cudaFuncAttributeMaxDynamicSharedMemorySize, SMEM_MM);
    cudaFuncSetAttribute(mma_gemm_kernel<1>, cudaFuncAttributeMaxDynamicSharedMemorySize, SMEM_MM);

    const dim3 gg(32, 32);
    const dim3 gcol(16, 32);
    const dim3 gtr(128, 128);
    const dim3 btr(32, 8);

    sqnorm_kernel<<<NDIM, 64>>>(fg, x2g);
    sqnorm_kernel<<<NDIM, 64>>>(fr, x2r);
    sgemm_kernel<2><<<gg, 256>>>(fg, fg, Dgen, x2g, x2g, nullptr);
    sgemm_kernel<2><<<gg, 256>>>(fr, fr, Dreal, x2r, x2r, nullptr);
    sgemm_kernel<3><<<gg, 256>>>(fg, fr, CW, x2g, x2r, part);
    reduce_max_kernel<<<1, 1024>>>(part, 1024, 0);           // cwmax

    row_sumsq_kernel<<<NDIM, 256>>>(Dgen, sg2);
    row_sumsq_kernel<<<NDIM, 256>>>(Dreal, sr2);
    row_sum_kernel<<<NDIM, 256>>>(Dgen, rg);
    row_sum_kernel<<<NDIM, 256>>>(Dreal, rr);                // symmetric -> colsum
    split3_kernel<<<4096, 256>>>(Dgen, Dgh, Dgm, Dgl);
    split3_kernel<<<4096, 256>>>(Dreal, Drh, Drm, Drl);      // symmetric -> B^T == B

    for (int it = 0; it < N_FGW; it++) {
        if (it == 0) {
            // coupling = a b^T is rank-1: closed-form CGW0
            gmax0_kernel<<<NDIM, 256>>>(part);
            reduce_max_kernel<<<1, 1024>>>(part, 4096, 1);   // gmax
            fusedmax_kernel<1><<<NDIM, 256>>>(part);
            reduce_max_kernel<<<1, 1024>>>(part, 4096, 2);   // cmax
            kexp_kernel<1><<<NDIM, 256>>>();
        } else {
            row_sum_kernel<<<NDIM, 256>>>(P, mu);
            colpart_sum_kernel<<<gcol, 256>>>(P);
            colfin_kernel<<<16, 256>>>(nu, 0);
            transpose_split3_kernel<<<gtr, btr>>>(P, Pth, Ptm, Ptl);
            mma_gemm_kernel<0><<<gg, 256, SMEM_MM>>>(Dgh, Dgm, Dgl, Pth, Ptm, Ptl,
                                                     Th, Tm, Tl, nullptr, nullptr);
            mma_gemm_kernel<1><<<gg, 256, SMEM_MM>>>(Th, Tm, Tl, Drh, Drm, Drl,
                                                     nullptr, nullptr, nullptr, CGW, part);
            reduce_max_kernel<<<1, 1024>>>(part, 1024, 1);   // gmax
            fusedmax_kernel<0><<<NDIM, 256>>>(part);
            reduce_max_kernel<<<1, 1024>>>(part, 4096, 2);   // cmax
            kexp_kernel<0><<<NDIM, 256>>>();
        }
        fill_kernel<<<16, 256>>>(v, 1.0f, (size_t)NDIM);
        for (int s = 0; s < N_SINK; s++) {
            sink_row_kernel<<<NDIM, 256>>>();
            sink_colpart_kernel<<<gcol, 256>>>();
            colfin_kernel<<<16, 256>>>(v, 1);
        }
        pwrite_kernel<<<NDIM, 256>>>(P, part);
        reduce_sum_kernel<<<1, 1024>>>(part, 4096, 3);       // S
        pscale_kernel<<<4096, 256>>>(P);
    }
    cfinal_kernel<<<4096, 256>>>(Cf);
}

// round 12
// speedup vs baseline: 1.5328x; 1.5328x over previous
#include <cuda_runtime.h>
#include <cuda_bf16.h>
#include <cstdint>
#include <cstddef>

#define NDIM 4096
#define DDIM 256
#define NMTOT ((size_t)NDIM * (size_t)NDIM)
#define EPS_R 0.05f
#define N_SINK 30
#define N_FGW 5

// ---------------- device scratch ----------------
__device__ float g_Dgen [NDIM * NDIM];
__device__ float g_Dreal[NDIM * NDIM];
__device__ float g_CW   [NDIM * NDIM];
__device__ float g_CGW  [NDIM * NDIM];
__device__ float g_Kmat [NDIM * NDIM];
__device__ __nv_bfloat16 g_Dg_h[NDIM * NDIM], g_Dg_l[NDIM * NDIM];
__device__ __nv_bfloat16 g_Dr_h[NDIM * NDIM], g_Dr_l[NDIM * NDIM];
__device__ __nv_bfloat16 g_Pt_h[NDIM * NDIM], g_Pt_l[NDIM * NDIM];
__device__ __nv_bfloat16 g_T_h [NDIM * NDIM], g_T_l [NDIM * NDIM];
__device__ float g_x2g[NDIM], g_x2r[NDIM];
__device__ float g_sg2[NDIM], g_sr2[NDIM];
__device__ float g_rg [NDIM], g_rr [NDIM];
__device__ float g_mu [NDIM], g_nu [NDIM];
__device__ float g_u  [NDIM], g_v  [NDIM];
__device__ float g_colpart[32 * NDIM];
__device__ float g_part[8192];
__device__ float g_scal[8];   // 0:cwmax 1:gmax 2:cmax 3:S

// ---------------- helpers ----------------
__device__ __forceinline__ uint32_t pack2(float f0, float f1) {
    __nv_bfloat162 p; p.x = __float2bfloat16(f0); p.y = __float2bfloat16(f1);
    return *reinterpret_cast<uint32_t*>(&p);
}
__device__ __forceinline__ void ldm_x4(uint32_t* r, uint32_t a) {
    asm volatile("ldmatrix.sync.aligned.m8n8.x4.shared.b16 {%0,%1,%2,%3}, [%4];"
        : "=r"(r[0]), "=r"(r[1]), "=r"(r[2]), "=r"(r[3]) : "r"(a));
}
__device__ __forceinline__ void mma16816(float* c, const uint32_t* a, const uint32_t* b) {
    asm volatile("mma.sync.aligned.m16n8k16.row.col.f32.bf16.bf16.f32 "
        "{%0,%1,%2,%3}, {%4,%5,%6,%7}, {%8,%9}, {%0,%1,%2,%3};"
        : "+f"(c[0]), "+f"(c[1]), "+f"(c[2]), "+f"(c[3])
        : "r"(a[0]), "r"(a[1]), "r"(a[2]), "r"(a[3]), "r"(b[0]), "r"(b[1]));
}
__device__ __forceinline__ uint32_t smem_u32(const void* p) {
    uint32_t a;
    asm("{ .reg .u64 t; cvta.to.shared.u64 t, %1; cvt.u32.u64 %0, t; }" : "=r"(a) : "l"(p));
    return a;
}
// 2-level split: x = h + l, |x-h-l| <= 2^-18 |x|
__device__ __forceinline__ void split2(float x, __nv_bfloat16& h, __nv_bfloat16& l) {
    h = __float2bfloat16(x);
    l = __float2bfloat16(x - __bfloat162float(h));
}
#define CP16(dst, src) asm volatile("cp.async.cg.shared.global [%0], [%1], 16;" :: "r"(dst), "l"(src) : "memory")
#define CPC() asm volatile("cp.async.commit_group;" ::: "memory")
#define CPW(n) asm volatile("cp.async.wait_group %0;" :: "n"(n) : "memory")

// ---------------- reductions ----------------
template<int BS>
__device__ __forceinline__ float bsum(float v) {
    static __shared__ float sh[BS];
    int t = threadIdx.x;
    sh[t] = v; __syncthreads();
#pragma unroll
    for (int s = BS / 2; s >= 64; s >>= 1) { if (t < s) sh[t] += sh[t + s]; __syncthreads(); }
    float x = 0.f;
    if (t < 32) {
        x = sh[t] + sh[t + 32];
#pragma unroll
        for (int o = 16; o; o >>= 1) x += __shfl_down_sync(0xffffffffu, x, o);
    }
    return x;
}
template<int BS>
__device__ __forceinline__ float bmax(float v) {
    static __shared__ float sh[BS];
    int t = threadIdx.x;
    sh[t] = v; __syncthreads();
#pragma unroll
    for (int s = BS / 2; s >= 64; s >>= 1) { if (t < s) sh[t] = fmaxf(sh[t], sh[t + s]); __syncthreads(); }
    float x = -3.402823466e38f;
    if (t < 32) {
        x = fmaxf(sh[t], sh[t + 32]);
#pragma unroll
        for (int o = 16; o; o >>= 1) x = fmaxf(x, __shfl_down_sync(0xffffffffu, x, o));
    }
    return x;
}

// ---------------- 3-term split bf16 GEMM, two-level accumulation ----------
// C[m,n] = sum_k A[m,k]*B[n,k], operands split into h+l (2-level, 2^-18).
// Terms kept: hh+hl+lh (dropped ll <= 2^-18|ab| -> absorbed by Sinkhorn).
// Working acc flushed into accS every 16 k-chunks (pairwise accumulation,
// the change that made R9/R10 pass). MODE 0: emit C re-split into Oh/Ol.
// MODE 1: CGW epilogue (t1+t2-2*t3) + block gmax.
#define STG_T 10240               // one tile: 128 rows * 80B (64B data + 16B pad)
#define STG_S (4 * STG_T)         // Ah,Al,Bh,Bl = 40960
#define SMEM_MM (3 * STG_S)       // 3 stages = 122880
#define BKT 32
#define NTILES (NDIM / BKT)       // 128

template<int MODE>
__global__ void __launch_bounds__(256, 1)
mma_gemm_kernel(const __nv_bfloat16* __restrict__ Ah_, const __nv_bfloat16* __restrict__ Al_,
                const __nv_bfloat16* __restrict__ Bh_, const __nv_bfloat16* __restrict__ Bl_,
                __nv_bfloat16* __restrict__ Oh, __nv_bfloat16* __restrict__ Ol,
                float* __restrict__ Cout, float* __restrict__ partials)
{
    extern __shared__ char smem[];
    const uint32_t sb = smem_u32(smem);
    const int tid = threadIdx.x, warp = tid >> 5, lane = tid & 31;
    const int bm = blockIdx.y << 7, bn = blockIdx.x << 7;
    const int wm = (warp >> 2) << 6, wn = (warp & 3) << 5;  // warp tile 64x32

    const char* srcs[4] = {
        (const char*)(Ah_ + (size_t)bm * NDIM), (const char*)(Al_ + (size_t)bm * NDIM),
        (const char*)(Bh_ + (size_t)bn * NDIM), (const char*)(Bl_ + (size_t)bn * NDIM) };

    auto load_stage = [&](int slot, int kt) {
        const uint32_t sbase = sb + slot * STG_S;
        const size_t ko = (size_t)kt * (BKT * 2);
#pragma unroll
        for (int i = 0; i < 8; i++) {
            const int tile = i >> 1;
            const int wc = ((i & 1) << 8) + tid;        // 0..511 within tile
            const int row = wc >> 2, cc = wc & 3;
            uint32_t dst = sbase + tile * STG_T + row * 80 + (cc << 4);
            const char* src = srcs[tile] + (size_t)row * (NDIM * 2) + ko + (cc << 4);
            CP16(dst, src);
        }
    };

    float acc[4][4][4], accS[4][4][4];
#pragma unroll
    for (int a = 0; a < 4; a++)
#pragma unroll
        for (int b = 0; b < 4; b++)
#pragma unroll
            for (int c = 0; c < 4; c++) { acc[a][b][c] = 0.f; accS[a][b][c] = 0.f; }

    load_stage(0, 0); CPC();
    load_stage(1, 1); CPC();

    const int grp = lane >> 3, l8 = lane & 7;

    for (int kt = 0; kt < NTILES; kt++) {
        CPW(1);
        __syncthreads();
        if (kt + 2 < NTILES) load_stage((kt + 2) % 3, kt + 2);
        CPC();
        const uint32_t stb = sb + (kt % 3) * STG_S;
#pragma unroll
        for (int ks = 0; ks < 2; ks++) {
            uint32_t ah[4][4], al[4][4], bh[4][2], bl[4][2], t[4];
            const uint32_t acol = (ks << 5) + ((grp >> 1) << 4);
#pragma unroll
            for (int mi = 0; mi < 4; mi++) {
                uint32_t ro = (uint32_t)(wm + (mi << 4) + ((grp & 1) << 3) + l8) * 80 + acol;
                ldm_x4(ah[mi], stb + 0 * STG_T + ro);
                ldm_x4(al[mi], stb + 1 * STG_T + ro);
            }
            const uint32_t bcol = (ks << 5) + ((grp & 1) << 4);
#pragma unroll
            for (int np = 0; np < 2; np++) {
                uint32_t ro = (uint32_t)(wn + (np << 4) + ((grp >> 1) << 3) + l8) * 80 + bcol;
                ldm_x4(t, stb + 2 * STG_T + ro);
                bh[2 * np][0] = t[0]; bh[2 * np][1] = t[1];
                bh[2 * np + 1][0] = t[2]; bh[2 * np + 1][1] = t[3];
                ldm_x4(t, stb + 3 * STG_T + ro);
                bl[2 * np][0] = t[0]; bl[2 * np][1] = t[1];
                bl[2 * np + 1][0] = t[2]; bl[2 * np + 1][1] = t[3];
            }
#pragma unroll
            for (int mi = 0; mi < 4; mi++)
#pragma unroll
                for (int ni = 0; ni < 4; ni++) {
                    mma16816(acc[mi][ni], ah[mi], bh[ni]);
                    mma16816(acc[mi][ni], ah[mi], bl[ni]);
                    mma16816(acc[mi][ni], al[mi], bh[ni]);
                }
        }
        if ((kt & 15) == 15) {   // pairwise flush: kills accumulation noise
#pragma unroll
            for (int a = 0; a < 4; a++)
#pragma unroll
                for (int b = 0; b < 4; b++)
#pragma unroll
                    for (int c = 0; c < 4; c++) { accS[a][b][c] += acc[a][b][c]; acc[a][b][c] = 0.f; }
        }
    }

    float lmax = 0.f;
#pragma unroll
    for (int mi = 0; mi < 4; mi++) {
        const int r1 = bm + wm + (mi << 4) + (lane >> 2);
        const int r2 = r1 + 8;
        float sgA = 0.f, muA = 0.f, sgB = 0.f, muB = 0.f;
        if (MODE == 1) { sgA = g_sg2[r1]; muA = g_mu[r1]; sgB = g_sg2[r2]; muB = g_mu[r2]; }
#pragma unroll
        for (int ni = 0; ni < 4; ni++) {
            const int n1 = bn + wn + (ni << 3) + ((lane & 3) << 1);
            const float c0 = accS[mi][ni][0], c1 = accS[mi][ni][1];
            const float c2 = accS[mi][ni][2], c3 = accS[mi][ni][3];
            if (MODE == 0) {
                __nv_bfloat16 h0, l0, h1, l1;
                split2(c0, h0, l0); split2(c1, h1, l1);
                __nv_bfloat162 ll01{l0, l1};
                *(uint32_t*)(Oh + (size_t)r1 * NDIM + n1) = pack2(c0, c1);
                *(uint32_t*)(Ol + (size_t)r1 * NDIM + n1) = *(uint32_t*)&ll01;
                __nv_bfloat16 h2, l2, h3, l3;
                split2(c2, h2, l2); split2(c3, h3, l3);
                __nv_bfloat162 ll23{l2, l3};
                *(uint32_t*)(Oh + (size_t)r2 * NDIM + n1) = pack2(c2, c3);
                *(uint32_t*)(Ol + (size_t)r2 * NDIM + n1) = *(uint32_t*)&ll23;
            } else {
                const float nu1 = g_nu[n1], nu2 = g_nu[n1 + 1];
                const float s1 = g_sr2[n1], s2 = g_sr2[n1 + 1];
                float v0 = sgA * nu1 + muA * s1 - 2.f * c0;
                float v1 = sgA * nu2 + muA * s2 - 2.f * c1;
                float v2 = sgB * nu1 + muB * s1 - 2.f * c2;
                float v3 = sgB * nu2 + muB * s2 - 2.f * c3;
                lmax = fmaxf(fmaxf(lmax, fabsf(v0)), fmaxf(fabsf(v1), fmaxf(fabsf(v2), fabsf(v3))));
                *(float2*)(Cout + (size_t)r1 * NDIM + n1) = make_float2(v0, v1);
                *(float2*)(Cout + (size_t)r2 * NDIM + n1) = make_float2(v2, v3);
            }
        }
    }
    if (MODE == 1) {
        float mm = bmax<256>(lmax);
        if (tid == 0) partials[blockIdx.y * gridDim.x + blockIdx.x] = mm;
    }
}

// ---------------- small kernels ----------------
__global__ void sqnorm_kernel(const float* __restrict__ X, float* __restrict__ out) {
    int i = blockIdx.x;
    float4 a = ((const float4*)(X + (size_t)i * DDIM))[threadIdx.x];
    float s = a.x * a.x + a.y * a.y + a.z * a.z + a.w * a.w;
    s = bsum<64>(s);
    if (threadIdx.x == 0) out[i] = s;
}

__global__ void fill_kernel(float* __restrict__ p, float val, size_t n) {
    size_t stride = (size_t)gridDim.x * blockDim.x;
    for (size_t i = (size_t)blockIdx.x * blockDim.x + threadIdx.x; i < n; i += stride) p[i] = val;
}

__global__ void row_sum_kernel(const float* __restrict__ M, float* __restrict__ out) {
    int i = blockIdx.x;
    const float4* rp = (const float4*)(M + (size_t)i * NDIM);
    float s = 0.f;
    for (int j = threadIdx.x; j < NDIM / 4; j += 256) { float4 a = rp[j]; s += a.x + a.y + a.z + a.w; }
    s = bsum<256>(s);
    if (threadIdx.x == 0) out[i] = s;
}

__global__ void row_sumsq_kernel(const float* __restrict__ M, float* __restrict__ out) {
    int i = blockIdx.x;
    const float4* rp = (const float4*)(M + (size_t)i * NDIM);
    float s = 0.f;
    for (int j = threadIdx.x; j < NDIM / 4; j += 256) {
        float4 a = rp[j];
        s += a.x * a.x + a.y * a.y + a.z * a.z + a.w * a.w;
    }
    s = bsum<256>(s);
    if (threadIdx.x == 0) out[i] = s;
}

__global__ void split2_kernel(const float* __restrict__ src, __nv_bfloat16* __restrict__ dh,
                              __nv_bfloat16* __restrict__ dl) {
    size_t stride = (size_t)gridDim.x * blockDim.x;
    const float2* sp = (const float2*)src;
    uint32_t* hp = (uint32_t*)dh; uint32_t* lp = (uint32_t*)dl;
    for (size_t i = (size_t)blockIdx.x * blockDim.x + threadIdx.x; i < NMTOT / 2; i += stride) {
        float2 f = sp[i];
        __nv_bfloat16 h0, l0, h1, l1;
        split2(f.x, h0, l0); split2(f.y, h1, l1);
        __nv_bfloat162 hh{h0, h1}, ll{l0, l1};
        hp[i] = *(uint32_t*)&hh; lp[i] = *(uint32_t*)&ll;
    }
}

__global__ void transpose_split2_kernel(const float* __restrict__ src,
                                        __nv_bfloat16* __restrict__ dh,
                                        __nv_bfloat16* __restrict__ dl) {
    __shared__ float tile[32][33];
    const int x0 = blockIdx.x << 5, y0 = blockIdx.y << 5;
    const int tx = threadIdx.x, ty = threadIdx.y;
#pragma unroll
    for (int r = ty; r < 32; r += 8)
        tile[r][tx] = src[(size_t)(y0 + r) * NDIM + x0 + tx];
    __syncthreads();
#pragma unroll
    for (int rn = ty; rn < 32; rn += 8) {
        float f = tile[tx][rn];
        __nv_bfloat16 h, l;
        split2(f, h, l);
        size_t o = (size_t)(x0 + rn) * NDIM + y0 + tx;
        dh[o] = h; dl[o] = l;
    }
}

__global__ void colpart_sum_kernel(const float* __restrict__ M) {
    int col = (blockIdx.x << 8) + threadIdx.x;
    int r0 = blockIdx.y << 7;
    const float* base = M + (size_t)r0 * NDIM + col;
    float s0 = 0.f, s1 = 0.f, s2 = 0.f, s3 = 0.f;
#pragma unroll 8
    for (int i = 0; i < 128; i += 4) {
        s0 += base[(size_t)(i + 0) * NDIM]; s1 += base[(size_t)(i + 1) * NDIM];
        s2 += base[(size_t)(i + 2) * NDIM]; s3 += base[(size_t)(i + 3) * NDIM];
    }
    g_colpart[(blockIdx.y << 12) + col] = (s0 + s1) + (s2 + s3);
}

__global__ void sink_colpart_kernel() {
    int col = (blockIdx.x << 8) + threadIdx.x;
    int r0 = blockIdx.y << 7;
    const float* base = g_Kmat + (size_t)r0 * NDIM + col;
    float s0 = 0.f, s1 = 0.f, s2 = 0.f, s3 = 0.f;
#pragma unroll 8
    for (int i = 0; i < 128; i += 4) {
        s0 += base[(size_t)(i + 0) * NDIM] * g_u[r0 + i + 0];
        s1 += base[(size_t)(i + 1) * NDIM] * g_u[r0 + i + 1];
        s2 += base[(size_t)(i + 2) * NDIM] * g_u[r0 + i + 2];
        s3 += base[(size_t)(i + 3) * NDIM] * g_u[r0 + i + 3];
    }
    g_colpart[(blockIdx.y << 12) + col] = (s0 + s1) + (s2 + s3);
}

__global__ void colfin_kernel(float* __restrict__ out, int isV) {
    int col = (blockIdx.x << 8) + threadIdx.x;
    float s = 0.f;
#pragma unroll
    for (int p = 0; p < 32; p++) s += g_colpart[(p << 12) + col];
    out[col] = isV ? ((1.0f / NDIM) / s) : s;
}

__global__ void sink_row_kernel() {
    int i = blockIdx.x;
    const float4* kr = (const float4*)(g_Kmat + (size_t)i * NDIM);
    const float4* vv = (const float4*)g_v;
    float s = 0.f;
    for (int j = threadIdx.x; j < NDIM / 4; j += 256) {
        float4 k = kr[j], w = vv[j];
        s += k.x * w.x + k.y * w.y + k.z * w.z + k.w * w.w;
    }
    s = bsum<256>(s);
    if (threadIdx.x == 0) g_u[i] = (1.0f / NDIM) / s;
}

__global__ void gmax0_kernel(float* __restrict__ partials) {
    const int i = blockIdx.x;
    const float invn = 1.0f / NDIM;
    const float ai = g_sg2[i] * invn;
    const float gi = 2.0f * g_rg[i] * invn * invn;
    const float4* sp = (const float4*)g_sr2;
    const float4* rp = (const float4*)g_rr;
    float m = 0.f;
    for (int j = threadIdx.x; j < NDIM / 4; j += 256) {
        float4 s = sp[j], rr = rp[j];
        m = fmaxf(m, fabsf(ai + s.x * invn - gi * rr.x));
        m = fmaxf(m, fabsf(ai + s.y * invn - gi * rr.y));
        m = fmaxf(m, fabsf(ai + s.z * invn - gi * rr.z));
        m = fmaxf(m, fabsf(ai + s.w * invn - gi * rr.w));
    }
    m = bmax<256>(m);
    if (threadIdx.x == 0) partials[i] = m;
}

template<int ITER0>
__global__ void fusedmax_kernel(float* __restrict__ partials) {
    const int i = blockIdx.x;
    const float invcw = (g_scal[0] > 0.f) ? 1.f / g_scal[0] : 1.f;
    const float invg  = (g_scal[1] > 0.f) ? 1.f / g_scal[1] : 1.f;
    const float invn = 1.0f / NDIM;
    const float ai = g_sg2[i] * invn;
    const float gi = 2.0f * g_rg[i] * invn * invn;
    const float4* cwp = (const float4*)(g_CW + (size_t)i * NDIM);
    const float4* cgp = (const float4*)(g_CGW + (size_t)i * NDIM);
    const float4* sp = (const float4*)g_sr2;
    const float4* rp = (const float4*)g_rr;
    float m = -3.402823466e38f;
    for (int j = threadIdx.x; j < NDIM / 4; j += 256) {
        float4 cw = cwp[j], cg;
        if (ITER0) {
            float4 s = sp[j], rr = rp[j];
            cg.x = ai + s.x * invn - gi * rr.x; cg.y = ai + s.y * invn - gi * rr.y;
            cg.z = ai + s.z * invn - gi * rr.z; cg.w = ai + s.w * invn - gi * rr.w;
        } else cg = cgp[j];
        m = fmaxf(m, 0.5f * cw.x * invcw + 0.5f * cg.x * invg);
        m = fmaxf(m, 0.5f * cw.y * invcw + 0.5f * cg.y * invg);
        m = fmaxf(m, 0.5f * cw.z * invcw + 0.5f * cg.z * invg);
        m = fmaxf(m, 0.5f * cw.w * invcw + 0.5f * cg.w * invg);
    }
    m = bmax<256>(m);
    if (threadIdx.x == 0) partials[i] = m;
}

template<int ITER0>
__global__ void kexp_kernel() {
    const int i = blockIdx.x;
    const float invcw = (g_scal[0] > 0.f) ? 1.f / g_scal[0] : 1.f;
    const float invg  = (g_scal[1] > 0.f) ? 1.f / g_scal[1] : 1.f;
    const float cm = g_scal[2];
    const float sc = (cm > 0.f) ? (-1.f / ((cm + 1e-8f) * EPS_R)) : (-1.f / EPS_R);
    const float invn = 1.0f / NDIM;
    const float ai = g_sg2[i] * invn;
    const float gi = 2.0f * g_rg[i] * invn * invn;
    const float4* cwp = (const float4*)(g_CW + (size_t)i * NDIM);
    const float4* cgp = (const float4*)(g_CGW + (size_t)i * NDIM);
    const float4* sp = (const float4*)g_sr2;
    const float4* rp = (const float4*)g_rr;
    float4* kp = (float4*)(g_Kmat + (size_t)i * NDIM);
    for (int j = threadIdx.x; j < NDIM / 4; j += 256) {
        float4 cw = cwp[j], cg;
        if (ITER0) {
            float4 s = sp[j], rr = rp[j];
            cg.x = ai + s.x * invn - gi * rr.x; cg.y = ai + s.y * invn - gi * rr.y;
            cg.z = ai + s.z * invn - gi * rr.z; cg.w = ai + s.w * invn - gi * rr.w;
        } else cg = cgp[j];
        float4 o;
        o.x = __expf((0.5f * cw.x * invcw + 0.5f * cg.x * invg) * sc);
        o.y = __expf((0.5f * cw.y * invcw + 0.5f * cg.y * invg) * sc);
        o.z = __expf((0.5f * cw.z * invcw + 0.5f * cg.z * invg) * sc);
        o.w = __expf((0.5f * cw.w * invcw + 0.5f * cg.w * invg) * sc);
        kp[j] = o;
    }
}

__global__ void pwrite_kernel(float* __restrict__ P, float* __restrict__ partials) {
    int i = blockIdx.x;
    float ui = g_u[i];
    const float4* kr = (const float4*)(g_Kmat + (size_t)i * NDIM);
    const float4* vv = (const float4*)g_v;
    float4* pr = (float4*)(P + (size_t)i * NDIM);
    float s = 0.f;
    for (int j = threadIdx.x; j < NDIM / 4; j += 256) {
        float4 k = kr[j], w = vv[j];
        float4 o;
        o.x = ui * k.x * w.x; o.y = ui * k.y * w.y; o.z = ui * k.z * w.z; o.w = ui * k.w * w.w;
        pr[j] = o;
        s += o.x + o.y + o.z + o.w;
    }
    s = bsum<256>(s);
    if (threadIdx.x == 0) partials[i] = s;
}

__global__ void pscale_kernel(float* __restrict__ P) {
    float sc = 1.0f / (g_scal[3] + 1e-10f);
    size_t stride = (size_t)gridDim.x * blockDim.x;
    float4* pp = (float4*)P;
    for (size_t i = (size_t)blockIdx.x * blockDim.x + threadIdx.x; i < NMTOT / 4; i += stride) {
        float4 a = pp[i];
        a.x *= sc; a.y *= sc; a.z *= sc; a.w *= sc;
        pp[i] = a;
    }
}

__global__ void cfinal_kernel(float* __restrict__ out) {
    size_t stride = (size_t)gridDim.x * blockDim.x;
    const float4* cwp = (const float4*)g_CW;
    const float4* cgp = (const float4*)g_CGW;
    float4* op = (float4*)out;
    for (size_t i = (size_t)blockIdx.x * blockDim.x + threadIdx.x; i < NMTOT / 4; i += stride) {
        float4 cw = cwp[i], cg = cgp[i];
        op[i] = make_float4(0.5f * cw.x + 0.5f * cg.x, 0.5f * cw.y + 0.5f * cg.y,
                            0.5f * cw.z + 0.5f * cg.z, 0.5f * cw.w + 0.5f * cg.w);
    }
}

__global__ void reduce_max_kernel(const float* __restrict__ part, int n, int slot) {
    float m = -3.402823466e38f;
    for (int i = threadIdx.x; i < n; i += 1024) m = fmaxf(m, part[i]);
    m = bmax<1024>(m);
    if (threadIdx.x == 0) g_scal[slot] = m;
}

__global__ void reduce_sum_kernel(const float* __restrict__ part, int n, int slot) {
    float s = 0.f;
    for (int i = threadIdx.x; i < n; i += 1024) s += part[i];
    s = bsum<1024>(s);
    if (threadIdx.x == 0) g_scal[slot] = s;
}

// ---------------- SIMT SGEMM over D=256 (cdist / CW only) -----------------
template<int MODE>  // 2: sqrt(relu) ; 3: relu + max
__global__ void __launch_bounds__(256, 2)
sgemm_kernel(const float* __restrict__ A, const float* __restrict__ B,
             float* __restrict__ C, const float* __restrict__ vx,
             const float* __restrict__ vy, float* __restrict__ partials)
{
    __shared__ float As[16][132];
    __shared__ float Bs[16][132];
    const int tid = threadIdx.x;
    const int bm = blockIdx.y << 7, bn = blockIdx.x << 7;
    const int ty = tid >> 4, tx = tid & 15;
    const int lr = tid >> 2, lc = tid & 3;

    float acc[8][8];
#pragma unroll
    for (int i = 0; i < 8; i++)
#pragma unroll
        for (int j = 0; j < 8; j++) acc[i][j] = 0.f;

    for (int k0 = 0; k0 < DDIM; k0 += 16) {
#pragma unroll
        for (int h = 0; h < 2; h++) {
            int row = lr + (h << 6);
            float4 a = *(const float4*)(A + (size_t)(bm + row) * DDIM + (k0 + (lc << 2)));
            As[(lc << 2) + 0][row] = a.x; As[(lc << 2) + 1][row] = a.y;
            As[(lc << 2) + 2][row] = a.z; As[(lc << 2) + 3][row] = a.w;
            float4 b = *(const float4*)(B + (size_t)(bn + row) * DDIM + (k0 + (lc << 2)));
            Bs[(lc << 2) + 0][row] = b.x; Bs[(lc << 2) + 1][row] = b.y;
            Bs[(lc << 2) + 2][row] = b.z; Bs[(lc << 2) + 3][row] = b.w;
        }
        __syncthreads();
#pragma unroll
        for (int kk = 0; kk < 16; kk++) {
            float av[8], bv[8];
            *(float4*)&av[0] = *(const float4*)&As[kk][ty << 3];
            *(float4*)&av[4] = *(const float4*)&As[kk][(ty << 3) + 4];
            *(float4*)&bv[0] = *(const float4*)&Bs[kk][tx << 3];
            *(float4*)&bv[4] = *(const float4*)&Bs[kk][(tx << 3) + 4];
#pragma unroll
            for (int i = 0; i < 8; i++)
#pragma unroll
                for (int j = 0; j < 8; j++)
                    acc[i][j] = fmaf(av[i], bv[j], acc[i][j]);
        }
        __syncthreads();
    }

    float lmax = 0.f;
#pragma unroll
    for (int i = 0; i < 8; i++) {
        int gi = bm + (ty << 3) + i;
        float p0 = vx[gi];
        float ov[8];
#pragma unroll
        for (int j = 0; j < 8; j++) {
            int gj = bn + (tx << 3) + j;
            float d2 = fmaxf(p0 + vy[gj] - 2.f * acc[i][j], 0.f);
            if (MODE == 2) ov[j] = (d2 > 0.f) ? sqrtf(d2) : 0.f;
            else { ov[j] = d2; lmax = fmaxf(lmax, d2); }
        }
        float4* cp = (float4*)(C + (size_t)gi * NDIM + bn + (tx << 3));
        cp[0] = *(float4*)&ov[0];
        cp[1] = *(float4*)&ov[4];
    }
    if (MODE == 3) {
        float m = bmax<256>(lmax);
        if (tid == 0) partials[blockIdx.y * gridDim.x + blockIdx.x] = m;
    }
}

// ---------------- launch --------------------------------------------------
extern "C" void kernel_launch(void* const* d_in, const int* in_sizes, int n_in,
                              void* d_out, int out_size) {
    const float* fg = (const float*)d_in[0];
    const float* fr = (const float*)d_in[1];
    float* P  = (float*)d_out;
    float* Cf = (float*)d_out + NMTOT;

    float *Dgen, *Dreal, *CW, *CGW, *x2g, *x2r, *sg2, *sr2, *rg, *rr, *mu, *nu, *v, *part;
    __nv_bfloat16 *Dgh, *Dgl, *Drh, *Drl, *Pth, *Ptl, *Th, *Tl;
    cudaGetSymbolAddress((void**)&Dgen, g_Dgen);   cudaGetSymbolAddress((void**)&Dreal, g_Dreal);
    cudaGetSymbolAddress((void**)&CW, g_CW);       cudaGetSymbolAddress((void**)&CGW, g_CGW);
    cudaGetSymbolAddress((void**)&x2g, g_x2g);     cudaGetSymbolAddress((void**)&x2r, g_x2r);
    cudaGetSymbolAddress((void**)&sg2, g_sg2);     cudaGetSymbolAddress((void**)&sr2, g_sr2);
    cudaGetSymbolAddress((void**)&rg, g_rg);       cudaGetSymbolAddress((void**)&rr, g_rr);
    cudaGetSymbolAddress((void**)&mu, g_mu);       cudaGetSymbolAddress((void**)&nu, g_nu);
    cudaGetSymbolAddress((void**)&v, g_v);         cudaGetSymbolAddress((void**)&part, g_part);
    cudaGetSymbolAddress((void**)&Dgh, g_Dg_h);    cudaGetSymbolAddress((void**)&Dgl, g_Dg_l);
    cudaGetSymbolAddress((void**)&Drh, g_Dr_h);    cudaGetSymbolAddress((void**)&Drl, g_Dr_l);
    cudaGetSymbolAddress((void**)&Pth, g_Pt_h);    cudaGetSymbolAddress((void**)&Ptl, g_Pt_l);
    cudaGetSymbolAddress((void**)&Th, g_T_h);      cudaGetSymbolAddress((void**)&Tl, g_T_l);

    cudaFuncSetAttribute(mma_gemm_kernel<0>, cudaFuncAttributeMaxDynamicSharedMemorySize, SMEM_MM);
    cudaFuncSetAttribute(mma_gemm_kernel<1>, cudaFuncAttributeMaxDynamicSharedMemorySize, SMEM_MM);

    const dim3 gg(32, 32);
    const dim3 gcol(16, 32);
    const dim3 gtr(128, 128);
    const dim3 btr(32, 8);

    sqnorm_kernel<<<NDIM, 64>>>(fg, x2g);
    sqnorm_kernel<<<NDIM, 64>>>(fr, x2r);
    sgemm_kernel<2><<<gg, 256>>>(fg, fg, Dgen, x2g, x2g, nullptr);
    sgemm_kernel<2><<<gg, 256>>>(fr, fr, Dreal, x2r, x2r, nullptr);
    sgemm_kernel<3><<<gg, 256>>>(fg, fr, CW, x2g, x2r, part);
    reduce_max_kernel<<<1, 1024>>>(part, 1024, 0);           // cwmax

    row_sumsq_kernel<<<NDIM, 256>>>(Dgen, sg2);
    row_sumsq_kernel<<<NDIM, 256>>>(Dreal, sr2);
    row_sum_kernel<<<NDIM, 256>>>(Dgen, rg);
    row_sum_kernel<<<NDIM, 256>>>(Dreal, rr);                // symmetric -> colsum
    split2_kernel<<<4096, 256>>>(Dgen, Dgh, Dgl);
    split2_kernel<<<4096, 256>>>(Dreal, Drh, Drl);           // symmetric -> B^T == B

    for (int it = 0; it < N_FGW; it++) {
        if (it == 0) {
            // coupling = a b^T is rank-1: closed-form CGW0
            gmax0_kernel<<<NDIM, 256>>>(part);
            reduce_max_kernel<<<1, 1024>>>(part, 4096, 1);   // gmax
            fusedmax_kernel<1><<<NDIM, 256>>>(part);
            reduce_max_kernel<<<1, 1024>>>(part, 4096, 2);   // cmax
            kexp_kernel<1><<<NDIM, 256>>>();
        } else {
            row_sum_kernel<<<NDIM, 256>>>(P, mu);
            colpart_sum_kernel<<<gcol, 256>>>(P);
            colfin_kernel<<<16, 256>>>(nu, 0);
            transpose_split2_kernel<<<gtr, btr>>>(P, Pth, Ptl);
            mma_gemm_kernel<0><<<gg, 256, SMEM_MM>>>(Dgh, Dgl, Pth, Ptl, Th, Tl, nullptr, nullptr);
            mma_gemm_kernel<1><<<gg, 256, SMEM_MM>>>(Th, Tl, Drh, Drl, nullptr, nullptr, CGW, part);
            reduce_max_kernel<<<1, 1024>>>(part, 1024, 1);   // gmax
            fusedmax_kernel<0><<<NDIM, 256>>>(part);
            reduce_max_kernel<<<1, 1024>>>(part, 4096, 2);   // cmax
            kexp_kernel<0><<<NDIM, 256>>>();
        }
        fill_kernel<<<16, 256>>>(v, 1.0f, (size_t)NDIM);
        for (int s = 0; s < N_SINK; s++) {
            sink_row_kernel<<<NDIM, 256>>>();
            sink_colpart_kernel<<<gcol, 256>>>();
            colfin_kernel<<<16, 256>>>(v, 1);
        }
        pwrite_kernel<<<NDIM, 256>>>(P, part);
        reduce_sum_kernel<<<1, 1024>>>(part, 4096, 3);       // S
        pscale_kernel<<<4096, 256>>>(P);
    }
    cfinal_kernel<<<4096, 256>>>(Cf);
}